// round 3
// baseline (speedup 1.0000x reference)
#include <cuda_runtime.h>

#define HH 512
#define WW 512
#define BB 8
#define PLANE (HH * WW)

// Tile geometry
#define TX 32
#define TY 8
#define EXW 36          // TX+4  (a/b extended grid, halo 2)
#define EXH 12          // TY+4
#define INW 40          // TX+8  (input region, halo 4)
#define INH 16          // TY+8

// smem layout (bytes):
//   region1 [0, 21312): input floats [6][16][41] (15744 B)  -> later ab float4 [3][12][37] (21312 B)
//   region2 [21312, 62640): vs floats [21][12][41] (41328 B) -> later vsab float4 [3][8][37] (14208 B)
#define R1_BYTES 21312
#define SMEM_BYTES 62640

#define SIN(ch, r, c)  smem[(ch) * (INH * 41) + (r) * 41 + (c)]
#define VS(ch, r, c)   smem[5328 + (ch) * (EXH * 41) + (r) * 41 + (c)]
#define AB(ch, r, c)   ((float4*)smem)[(ch) * (EXH * 37) + (r) * 37 + (c)]
#define VSAB(ch, r, c) ((float4*)smem)[1332 + (ch) * (TY * 37) + (r) * 37 + (c)]

__device__ __forceinline__ int refl(int q, int n) {
    if (q < 0) q = -q;
    if (q >= n) q = 2 * n - 2 - q;
    return q;
}

__device__ __forceinline__ float4 f4add(float4 a, float4 b) {
    return make_float4(a.x + b.x, a.y + b.y, a.z + b.z, a.w + b.w);
}

__global__ __launch_bounds__(256)
void gf_fused(const float* __restrict__ gd, const float* __restrict__ pd,
              float* __restrict__ out) {
    extern __shared__ float smem[];

    const int b = blockIdx.z;
    const int x0 = blockIdx.x * TX, y0 = blockIdx.y * TY;
    const int tx = threadIdx.x, ty = threadIdx.y;
    const int tid = ty * TX + tx;
    const int bbase = b * 3 * PLANE;

    // ---------- Phase L: load 6 base channels with reflect, halo 4 ----------
    for (int i = tid; i < INH * INW; i += 256) {
        const int r = i / INW, c = i % INW;
        const int gy = refl(y0 + r - 4, HH);
        const int gx = refl(x0 + c - 4, WW);
        const int o = bbase + gy * WW + gx;
#pragma unroll
        for (int ch = 0; ch < 3; ch++) {
            SIN(ch, r, c)     = gd[o + ch * PLANE];
            SIN(3 + ch, r, c) = pd[o + ch * PLANE];
        }
    }
    __syncthreads();

    // Guidance at this thread's output pixel (input region coords +4).
    const float gc0 = SIN(0, ty + 4, tx + 4);
    const float gc1 = SIN(1, ty + 4, tx + 4);
    const float gc2 = SIN(2, ty + 4, tx + 4);

    // ---------- Phase A: vertical 5-tap product sums at EXH rows x INW cols ----------
    for (int i = tid; i < EXH * INW; i += 256) {
        const int r = i / INW, c = i % INW;
        float a[21];
#pragma unroll
        for (int k = 0; k < 21; k++) a[k] = 0.f;
#pragma unroll
        for (int dy = 0; dy < 5; dy++) {
            const float g0 = SIN(0, r + dy, c);
            const float g1 = SIN(1, r + dy, c);
            const float g2 = SIN(2, r + dy, c);
            const float p0 = SIN(3, r + dy, c);
            const float p1 = SIN(4, r + dy, c);
            const float p2 = SIN(5, r + dy, c);
            a[0] += g0; a[1] += g1; a[2] += g2;
            a[3] += p0; a[4] += p1; a[5] += p2;
            a[6]  += g0 * g0; a[7]  += g0 * g1; a[8]  += g0 * g2;
            a[9]  += g1 * g1; a[10] += g1 * g2; a[11] += g2 * g2;
            a[12] += g0 * p0; a[13] += g0 * p1; a[14] += g0 * p2;
            a[15] += g1 * p0; a[16] += g1 * p1; a[17] += g1 * p2;
            a[18] += g2 * p0; a[19] += g2 * p1; a[20] += g2 * p2;
        }
#pragma unroll
        for (int k = 0; k < 21; k++) VS(k, r, c) = a[k];
    }
    __syncthreads();

    // ---------- Phase B: horizontal 5-tap + 3x3 solve at EXH x EXW positions ----------
    // (writes AB, which overlays the now-dead input region)
    for (int i = tid; i < EXH * EXW; i += 256) {
        const int r = i / EXW, c = i % EXW;
        float m[21];
#pragma unroll
        for (int k = 0; k < 21; k++)
            m[k] = VS(k, r, c) + VS(k, r, c + 1) + VS(k, r, c + 2)
                 + VS(k, r, c + 3) + VS(k, r, c + 4);

        const float inv = 1.0f / 25.0f;
        const float eps = 1e-4f;
        const float mI0 = m[0] * inv, mI1 = m[1] * inv, mI2 = m[2] * inv;
        const float mp0 = m[3] * inv, mp1 = m[4] * inv, mp2 = m[5] * inv;

        const float a00 = m[6]  * inv - mI0 * mI0 + eps;
        const float a01 = m[7]  * inv - mI0 * mI1;
        const float a02 = m[8]  * inv - mI0 * mI2;
        const float a11 = m[9]  * inv - mI1 * mI1 + eps;
        const float a12 = m[10] * inv - mI1 * mI2;
        const float a22 = m[11] * inv - mI2 * mI2 + eps;

        const float c00 = m[12] * inv - mI0 * mp0, c01 = m[13] * inv - mI0 * mp1, c02 = m[14] * inv - mI0 * mp2;
        const float c10 = m[15] * inv - mI1 * mp0, c11 = m[16] * inv - mI1 * mp1, c12 = m[17] * inv - mI1 * mp2;
        const float c20 = m[18] * inv - mI2 * mp0, c21 = m[19] * inv - mI2 * mp1, c22 = m[20] * inv - mI2 * mp2;

        float i00 = a11 * a22 - a12 * a12;
        float i01 = a02 * a12 - a01 * a22;
        float i02 = a01 * a12 - a02 * a11;
        float i11 = a00 * a22 - a02 * a02;
        float i12 = a01 * a02 - a00 * a12;
        float i22 = a00 * a11 - a01 * a01;
        const float det = a00 * i00 + a01 * i01 + a02 * i02;
        const float rd = 1.0f / det;
        i00 *= rd; i01 *= rd; i02 *= rd; i11 *= rd; i12 *= rd; i22 *= rd;

        const float A00 = i00 * c00 + i01 * c10 + i02 * c20;
        const float A01 = i00 * c01 + i01 * c11 + i02 * c21;
        const float A02 = i00 * c02 + i01 * c12 + i02 * c22;
        const float A10 = i01 * c00 + i11 * c10 + i12 * c20;
        const float A11 = i01 * c01 + i11 * c11 + i12 * c21;
        const float A12 = i01 * c02 + i11 * c12 + i12 * c22;
        const float A20 = i02 * c00 + i12 * c10 + i22 * c20;
        const float A21 = i02 * c01 + i12 * c11 + i22 * c21;
        const float A22 = i02 * c02 + i12 * c12 + i22 * c22;

        const float b0 = mp0 - (A00 * mI0 + A10 * mI1 + A20 * mI2);
        const float b1 = mp1 - (A01 * mI0 + A11 * mI1 + A21 * mI2);
        const float b2 = mp2 - (A02 * mI0 + A12 * mI1 + A22 * mI2);

        AB(0, r, c) = make_float4(A00, A01, A02, A10);
        AB(1, r, c) = make_float4(A11, A12, A20, A21);
        AB(2, r, c) = make_float4(A22, b0, b1, b2);
    }
    __syncthreads();

    // ---------- Phase C: vertical 5-tap sums of a/b (writes VSAB over dead VS) ----------
    for (int i = tid; i < TY * EXW; i += 256) {
        const int r = i / EXW, c = i % EXW;
#pragma unroll
        for (int ch = 0; ch < 3; ch++) {
            float4 s = AB(ch, r, c);
            s = f4add(s, AB(ch, r + 1, c));
            s = f4add(s, AB(ch, r + 2, c));
            s = f4add(s, AB(ch, r + 3, c));
            s = f4add(s, AB(ch, r + 4, c));
            VSAB(ch, r, c) = s;
        }
    }
    __syncthreads();

    // ---------- Phase D: horizontal 5-tap + combine ----------
    float4 m0 = VSAB(0, ty, tx);
    m0 = f4add(m0, VSAB(0, ty, tx + 1)); m0 = f4add(m0, VSAB(0, ty, tx + 2));
    m0 = f4add(m0, VSAB(0, ty, tx + 3)); m0 = f4add(m0, VSAB(0, ty, tx + 4));
    float4 m1 = VSAB(1, ty, tx);
    m1 = f4add(m1, VSAB(1, ty, tx + 1)); m1 = f4add(m1, VSAB(1, ty, tx + 2));
    m1 = f4add(m1, VSAB(1, ty, tx + 3)); m1 = f4add(m1, VSAB(1, ty, tx + 4));
    float4 m2 = VSAB(2, ty, tx);
    m2 = f4add(m2, VSAB(2, ty, tx + 1)); m2 = f4add(m2, VSAB(2, ty, tx + 2));
    m2 = f4add(m2, VSAB(2, ty, tx + 3)); m2 = f4add(m2, VSAB(2, ty, tx + 4));

    const float inv = 1.0f / 25.0f;
    const int o = bbase + (y0 + ty) * WW + (x0 + tx);
    out[o]             = (gc0 * m0.x + gc1 * m0.w + gc2 * m1.z + m2.y) * inv;
    out[o + PLANE]     = (gc0 * m0.y + gc1 * m1.x + gc2 * m1.w + m2.z) * inv;
    out[o + 2 * PLANE] = (gc0 * m0.z + gc1 * m1.y + gc2 * m2.x + m2.w) * inv;
}

extern "C" void kernel_launch(void* const* d_in, const int* in_sizes, int n_in,
                              void* d_out, int out_size) {
    const float* gd = (const float*)d_in[0];
    const float* pd = (const float*)d_in[1];
    float* out = (float*)d_out;

    cudaFuncSetAttribute(gf_fused, cudaFuncAttributeMaxDynamicSharedMemorySize, SMEM_BYTES);

    dim3 grid(WW / TX, HH / TY, BB);
    dim3 blk(TX, TY);
    gf_fused<<<grid, blk, SMEM_BYTES>>>(gd, pd, out);
}

// round 4
// speedup vs baseline: 1.4585x; 1.4585x over previous
#include <cuda_runtime.h>

#define HH 512
#define WW 512
#define BB 8
#define PLANE (HH * WW)
#define CPW 28      // output columns per warp (32 lanes - 4 halo)
#define SEG 32      // rows swept per block
#define NWARP 4     // warps per block

// Scratch: a/b coefficients, three float4 planes (channel-planar, coalesced).
// f4_0={A00,A01,A02,A10} f4_1={A11,A12,A20,A21} f4_2={A22,b0,b1,b2}
__device__ float4 g_scr0[BB * PLANE];
__device__ float4 g_scr1[BB * PLANE];
__device__ float4 g_scr2[BB * PLANE];

__device__ __forceinline__ int refl(int q, int n) {
    if (q < 0) q = -q;
    if (q >= n) q = 2 * n - 2 - q;
    return q;
}

// Horizontal 5-tap sum across warp lanes (lane = column): 3 shuffles.
__device__ __forceinline__ float hsum5(float v) {
    const unsigned m = 0xffffffffu;
    float s1 = v + __shfl_down_sync(m, v, 1);                 // v(x)+v(x+1)
    return __shfl_up_sync(m, s1, 2) + s1 + __shfl_down_sync(m, v, 2);
}

// Accumulate (+/-) the 21 per-row products at row offset o into vs[21].
template<bool ADD>
__device__ __forceinline__ void accum6(float vs[21],
                                       const float* __restrict__ gb,
                                       const float* __restrict__ pb, int o) {
    const float s = ADD ? 1.f : -1.f;
    const float g0 = __ldg(gb + o), g1 = __ldg(gb + o + PLANE), g2 = __ldg(gb + o + 2 * PLANE);
    const float p0 = __ldg(pb + o), p1 = __ldg(pb + o + PLANE), p2 = __ldg(pb + o + 2 * PLANE);
    const float sg0 = s * g0, sg1 = s * g1, sg2 = s * g2;
    const float sp0 = s * p0, sp1 = s * p1, sp2 = s * p2;
    vs[0] += sg0; vs[1] += sg1; vs[2] += sg2;
    vs[3] += sp0; vs[4] += sp1; vs[5] += sp2;
    vs[6]  = fmaf(sg0, g0, vs[6]);  vs[7]  = fmaf(sg0, g1, vs[7]);  vs[8]  = fmaf(sg0, g2, vs[8]);
    vs[9]  = fmaf(sg1, g1, vs[9]);  vs[10] = fmaf(sg1, g2, vs[10]); vs[11] = fmaf(sg2, g2, vs[11]);
    vs[12] = fmaf(sg0, p0, vs[12]); vs[13] = fmaf(sg0, p1, vs[13]); vs[14] = fmaf(sg0, p2, vs[14]);
    vs[15] = fmaf(sg1, p0, vs[15]); vs[16] = fmaf(sg1, p1, vs[16]); vs[17] = fmaf(sg1, p2, vs[17]);
    vs[18] = fmaf(sg2, p0, vs[18]); vs[19] = fmaf(sg2, p1, vs[19]); vs[20] = fmaf(sg2, p2, vs[20]);
}

// ---------------- Stage 1: product box-blur (register sweep) + 3x3 solve ----------------
__global__ __launch_bounds__(NWARP * 32)
void gf_s1(const float* __restrict__ gd, const float* __restrict__ pd) {
    const int b = blockIdx.z;
    const int lane = threadIdx.x & 31;
    const int warp = threadIdx.x >> 5;
    const int tile = blockIdx.x * NWARP + warp;
    const int xout0 = tile * CPW;
    if (xout0 >= WW) return;                    // warp-uniform
    const int x = xout0 + lane - 2;             // this lane's column
    const int xr = refl(x, WW);
    const int y0 = blockIdx.y * SEG;

    const float* gb = gd + b * 3 * PLANE + xr;
    const float* pb = pd + b * 3 * PLANE + xr;

    float vs[21];
#pragma unroll
    for (int k = 0; k < 21; k++) vs[k] = 0.f;

    // preload rows y0-2 .. y0+1
#pragma unroll
    for (int dy = -2; dy < 2; dy++)
        accum6<true>(vs, gb, pb, refl(y0 + dy, HH) * WW);

    const bool valid = (lane >= 2) && (lane < 30) && (x < WW);
    const int bpix0 = b * PLANE + x;

    for (int y = y0; y < y0 + SEG; y++) {
        accum6<true>(vs, gb, pb, refl(y + 2, HH) * WW);

        float m[21];
#pragma unroll
        for (int k = 0; k < 21; k++) m[k] = hsum5(vs[k]);

        const float inv = 1.0f / 25.0f;
        const float eps = 1e-4f;
        const float mI0 = m[0] * inv, mI1 = m[1] * inv, mI2 = m[2] * inv;
        const float mp0 = m[3] * inv, mp1 = m[4] * inv, mp2 = m[5] * inv;

        const float a00 = m[6]  * inv - mI0 * mI0 + eps;
        const float a01 = m[7]  * inv - mI0 * mI1;
        const float a02 = m[8]  * inv - mI0 * mI2;
        const float a11 = m[9]  * inv - mI1 * mI1 + eps;
        const float a12 = m[10] * inv - mI1 * mI2;
        const float a22 = m[11] * inv - mI2 * mI2 + eps;

        const float c00 = m[12] * inv - mI0 * mp0, c01 = m[13] * inv - mI0 * mp1, c02 = m[14] * inv - mI0 * mp2;
        const float c10 = m[15] * inv - mI1 * mp0, c11 = m[16] * inv - mI1 * mp1, c12 = m[17] * inv - mI1 * mp2;
        const float c20 = m[18] * inv - mI2 * mp0, c21 = m[19] * inv - mI2 * mp1, c22 = m[20] * inv - mI2 * mp2;

        float i00 = a11 * a22 - a12 * a12;
        float i01 = a02 * a12 - a01 * a22;
        float i02 = a01 * a12 - a02 * a11;
        float i11 = a00 * a22 - a02 * a02;
        float i12 = a01 * a02 - a00 * a12;
        float i22 = a00 * a11 - a01 * a01;
        const float det = a00 * i00 + a01 * i01 + a02 * i02;
        const float rd = 1.0f / det;
        i00 *= rd; i01 *= rd; i02 *= rd; i11 *= rd; i12 *= rd; i22 *= rd;

        const float A00 = i00 * c00 + i01 * c10 + i02 * c20;
        const float A01 = i00 * c01 + i01 * c11 + i02 * c21;
        const float A02 = i00 * c02 + i01 * c12 + i02 * c22;
        const float A10 = i01 * c00 + i11 * c10 + i12 * c20;
        const float A11 = i01 * c01 + i11 * c11 + i12 * c21;
        const float A12 = i01 * c02 + i11 * c12 + i12 * c22;
        const float A20 = i02 * c00 + i12 * c10 + i22 * c20;
        const float A21 = i02 * c01 + i12 * c11 + i22 * c21;
        const float A22 = i02 * c02 + i12 * c12 + i22 * c22;

        const float b0 = mp0 - (A00 * mI0 + A10 * mI1 + A20 * mI2);
        const float b1 = mp1 - (A01 * mI0 + A11 * mI1 + A21 * mI2);
        const float b2 = mp2 - (A02 * mI0 + A12 * mI1 + A22 * mI2);

        if (valid) {
            const int bpix = bpix0 + y * WW;
            g_scr0[bpix] = make_float4(A00, A01, A02, A10);
            g_scr1[bpix] = make_float4(A11, A12, A20, A21);
            g_scr2[bpix] = make_float4(A22, b0, b1, b2);
        }

        accum6<false>(vs, gb, pb, refl(y - 2, HH) * WW);
    }
}

// Accumulate (+/-) one a/b row into vs[12].
template<bool ADD>
__device__ __forceinline__ void accumAB(float vs[12], int bpix) {
    const float4 v0 = __ldg(&g_scr0[bpix]);
    const float4 v1 = __ldg(&g_scr1[bpix]);
    const float4 v2 = __ldg(&g_scr2[bpix]);
    if (ADD) {
        vs[0] += v0.x; vs[1] += v0.y; vs[2]  += v0.z; vs[3]  += v0.w;
        vs[4] += v1.x; vs[5] += v1.y; vs[6]  += v1.z; vs[7]  += v1.w;
        vs[8] += v2.x; vs[9] += v2.y; vs[10] += v2.z; vs[11] += v2.w;
    } else {
        vs[0] -= v0.x; vs[1] -= v0.y; vs[2]  -= v0.z; vs[3]  -= v0.w;
        vs[4] -= v1.x; vs[5] -= v1.y; vs[6]  -= v1.z; vs[7]  -= v1.w;
        vs[8] -= v2.x; vs[9] -= v2.y; vs[10] -= v2.z; vs[11] -= v2.w;
    }
}

// ---------------- Stage 2: a/b box-blur (register sweep) + combine ----------------
__global__ __launch_bounds__(NWARP * 32)
void gf_s2(const float* __restrict__ gd, float* __restrict__ out) {
    const int b = blockIdx.z;
    const int lane = threadIdx.x & 31;
    const int warp = threadIdx.x >> 5;
    const int tile = blockIdx.x * NWARP + warp;
    const int xout0 = tile * CPW;
    if (xout0 >= WW) return;
    const int x = xout0 + lane - 2;
    const int xr = refl(x, WW);
    const int y0 = blockIdx.y * SEG;
    const int base = b * PLANE + xr;

    float vs[12];
#pragma unroll
    for (int k = 0; k < 12; k++) vs[k] = 0.f;

#pragma unroll
    for (int dy = -2; dy < 2; dy++)
        accumAB<true>(vs, base + refl(y0 + dy, HH) * WW);

    const bool valid = (lane >= 2) && (lane < 30) && (x < WW);
    const float* gb = gd + b * 3 * PLANE + x;
    float* ob = out + b * 3 * PLANE + x;

    for (int y = y0; y < y0 + SEG; y++) {
        accumAB<true>(vs, base + refl(y + 2, HH) * WW);

        float M[12];
#pragma unroll
        for (int k = 0; k < 12; k++) M[k] = hsum5(vs[k]);

        if (valid) {
            const int o = y * WW;
            const float g0 = __ldg(gb + o);
            const float g1 = __ldg(gb + o + PLANE);
            const float g2 = __ldg(gb + o + 2 * PLANE);
            const float inv = 1.0f / 25.0f;
            ob[o]             = (g0 * M[0] + g1 * M[3] + g2 * M[6] + M[9])  * inv;
            ob[o + PLANE]     = (g0 * M[1] + g1 * M[4] + g2 * M[7] + M[10]) * inv;
            ob[o + 2 * PLANE] = (g0 * M[2] + g1 * M[5] + g2 * M[8] + M[11]) * inv;
        }

        accumAB<false>(vs, base + refl(y - 2, HH) * WW);
    }
}

extern "C" void kernel_launch(void* const* d_in, const int* in_sizes, int n_in,
                              void* d_out, int out_size) {
    const float* gd = (const float*)d_in[0];
    const float* pd = (const float*)d_in[1];
    float* out = (float*)d_out;

    const int tiles = (WW + CPW - 1) / CPW;            // 19
    const int gx = (tiles + NWARP - 1) / NWARP;        // 5
    dim3 grid(gx, HH / SEG, BB);
    dim3 blk(NWARP * 32);
    gf_s1<<<grid, blk>>>(gd, pd);
    gf_s2<<<grid, blk>>>(gd, out);
}

// round 5
// speedup vs baseline: 1.9240x; 1.3191x over previous
#include <cuda_runtime.h>

#define HH 512
#define WW 512
#define BB 8
#define PLANE (HH * WW)
#define CPW 28      // output columns per warp (32 lanes - 4 halo)
#define SEG 16      // rows swept per block
#define NWARP 4     // warps per block

// Scratch: a/b coefficients, three float4 planes (channel-planar, coalesced).
// f4_0={A00,A01,A02,A10} f4_1={A11,A12,A20,A21} f4_2={A22,b0,b1,b2}
__device__ float4 g_scr0[BB * PLANE];
__device__ float4 g_scr1[BB * PLANE];
__device__ float4 g_scr2[BB * PLANE];

__device__ __forceinline__ int refl(int q, int n) {
    if (q < 0) q = -q;
    if (q >= n) q = 2 * n - 2 - q;
    return q;
}

// Horizontal 5-tap sum across warp lanes (lane = column): 3 shuffles.
__device__ __forceinline__ float hsum5(float v) {
    const unsigned m = 0xffffffffu;
    float s1 = v + __shfl_down_sync(m, v, 1);                 // v(x)+v(x+1)
    return __shfl_up_sync(m, s1, 2) + s1 + __shfl_down_sync(m, v, 2);
}

struct Row6 { float g0, g1, g2, p0, p1, p2; };

__device__ __forceinline__ Row6 load6(const float* __restrict__ gb,
                                      const float* __restrict__ pb, int o) {
    Row6 r;
    r.g0 = __ldg(gb + o); r.g1 = __ldg(gb + o + PLANE); r.g2 = __ldg(gb + o + 2 * PLANE);
    r.p0 = __ldg(pb + o); r.p1 = __ldg(pb + o + PLANE); r.p2 = __ldg(pb + o + 2 * PLANE);
    return r;
}

template<bool ADD>
__device__ __forceinline__ void apply6(float vs[21], const Row6& r) {
    const float s = ADD ? 1.f : -1.f;
    const float sg0 = s * r.g0, sg1 = s * r.g1, sg2 = s * r.g2;
    const float sp0 = s * r.p0, sp1 = s * r.p1, sp2 = s * r.p2;
    vs[0] += sg0; vs[1] += sg1; vs[2] += sg2;
    vs[3] += sp0; vs[4] += sp1; vs[5] += sp2;
    vs[6]  = fmaf(sg0, r.g0, vs[6]);  vs[7]  = fmaf(sg0, r.g1, vs[7]);  vs[8]  = fmaf(sg0, r.g2, vs[8]);
    vs[9]  = fmaf(sg1, r.g1, vs[9]);  vs[10] = fmaf(sg1, r.g2, vs[10]); vs[11] = fmaf(sg2, r.g2, vs[11]);
    vs[12] = fmaf(sg0, r.p0, vs[12]); vs[13] = fmaf(sg0, r.p1, vs[13]); vs[14] = fmaf(sg0, r.p2, vs[14]);
    vs[15] = fmaf(sg1, r.p0, vs[15]); vs[16] = fmaf(sg1, r.p1, vs[16]); vs[17] = fmaf(sg1, r.p2, vs[17]);
    vs[18] = fmaf(sg2, r.p0, vs[18]); vs[19] = fmaf(sg2, r.p1, vs[19]); vs[20] = fmaf(sg2, r.p2, vs[20]);
}

// ---------------- Stage 1: product box-blur (register sweep) + 3x3 solve ----------------
__global__ __launch_bounds__(NWARP * 32)
void gf_s1(const float* __restrict__ gd, const float* __restrict__ pd) {
    const int b = blockIdx.z;
    const int lane = threadIdx.x & 31;
    const int warp = threadIdx.x >> 5;
    const int tile = blockIdx.x * NWARP + warp;
    const int xout0 = tile * CPW;
    if (xout0 >= WW) return;                    // warp-uniform
    const int x = xout0 + lane - 2;             // this lane's column
    const int xr = refl(x, WW);
    const int y0 = blockIdx.y * SEG;

    const float* gb = gd + b * 3 * PLANE + xr;
    const float* pb = pd + b * 3 * PLANE + xr;

    float vs[21];
#pragma unroll
    for (int k = 0; k < 21; k++) vs[k] = 0.f;

    // preload rows y0-2 .. y0+1
#pragma unroll
    for (int dy = -2; dy < 2; dy++) {
        Row6 r = load6(gb, pb, refl(y0 + dy, HH) * WW);
        apply6<true>(vs, r);
    }

    const bool valid = (lane >= 2) && (lane < 30) && (x < WW);
    const int bpix0 = b * PLANE + x;

    for (int y = y0; y < y0 + SEG; y++) {
        // Batch entering & leaving row loads (MLP 12) before any use.
        Row6 radd = load6(gb, pb, refl(y + 2, HH) * WW);
        Row6 rsub = load6(gb, pb, refl(y - 2, HH) * WW);
        apply6<true>(vs, radd);

        float m[21];
#pragma unroll
        for (int k = 0; k < 21; k++) m[k] = hsum5(vs[k]);

        const float inv = 1.0f / 25.0f;
        const float eps = 1e-4f;
        const float mI0 = m[0] * inv, mI1 = m[1] * inv, mI2 = m[2] * inv;
        const float mp0 = m[3] * inv, mp1 = m[4] * inv, mp2 = m[5] * inv;

        const float a00 = m[6]  * inv - mI0 * mI0 + eps;
        const float a01 = m[7]  * inv - mI0 * mI1;
        const float a02 = m[8]  * inv - mI0 * mI2;
        const float a11 = m[9]  * inv - mI1 * mI1 + eps;
        const float a12 = m[10] * inv - mI1 * mI2;
        const float a22 = m[11] * inv - mI2 * mI2 + eps;

        const float c00 = m[12] * inv - mI0 * mp0, c01 = m[13] * inv - mI0 * mp1, c02 = m[14] * inv - mI0 * mp2;
        const float c10 = m[15] * inv - mI1 * mp0, c11 = m[16] * inv - mI1 * mp1, c12 = m[17] * inv - mI1 * mp2;
        const float c20 = m[18] * inv - mI2 * mp0, c21 = m[19] * inv - mI2 * mp1, c22 = m[20] * inv - mI2 * mp2;

        float i00 = a11 * a22 - a12 * a12;
        float i01 = a02 * a12 - a01 * a22;
        float i02 = a01 * a12 - a02 * a11;
        float i11 = a00 * a22 - a02 * a02;
        float i12 = a01 * a02 - a00 * a12;
        float i22 = a00 * a11 - a01 * a01;
        const float det = a00 * i00 + a01 * i01 + a02 * i02;
        const float rd = 1.0f / det;
        i00 *= rd; i01 *= rd; i02 *= rd; i11 *= rd; i12 *= rd; i22 *= rd;

        const float A00 = i00 * c00 + i01 * c10 + i02 * c20;
        const float A01 = i00 * c01 + i01 * c11 + i02 * c21;
        const float A02 = i00 * c02 + i01 * c12 + i02 * c22;
        const float A10 = i01 * c00 + i11 * c10 + i12 * c20;
        const float A11 = i01 * c01 + i11 * c11 + i12 * c21;
        const float A12 = i01 * c02 + i11 * c12 + i12 * c22;
        const float A20 = i02 * c00 + i12 * c10 + i22 * c20;
        const float A21 = i02 * c01 + i12 * c11 + i22 * c21;
        const float A22 = i02 * c02 + i12 * c12 + i22 * c22;

        const float b0 = mp0 - (A00 * mI0 + A10 * mI1 + A20 * mI2);
        const float b1 = mp1 - (A01 * mI0 + A11 * mI1 + A21 * mI2);
        const float b2 = mp2 - (A02 * mI0 + A12 * mI1 + A22 * mI2);

        if (valid) {
            const int bpix = bpix0 + y * WW;
            g_scr0[bpix] = make_float4(A00, A01, A02, A10);
            g_scr1[bpix] = make_float4(A11, A12, A20, A21);
            g_scr2[bpix] = make_float4(A22, b0, b1, b2);
        }

        apply6<false>(vs, rsub);
    }
}

struct RowAB { float4 v0, v1, v2; };

__device__ __forceinline__ RowAB loadAB(int bpix) {
    RowAB r;
    r.v0 = __ldg(&g_scr0[bpix]);
    r.v1 = __ldg(&g_scr1[bpix]);
    r.v2 = __ldg(&g_scr2[bpix]);
    return r;
}

template<bool ADD>
__device__ __forceinline__ void applyAB(float vs[12], const RowAB& r) {
    if (ADD) {
        vs[0] += r.v0.x; vs[1] += r.v0.y; vs[2]  += r.v0.z; vs[3]  += r.v0.w;
        vs[4] += r.v1.x; vs[5] += r.v1.y; vs[6]  += r.v1.z; vs[7]  += r.v1.w;
        vs[8] += r.v2.x; vs[9] += r.v2.y; vs[10] += r.v2.z; vs[11] += r.v2.w;
    } else {
        vs[0] -= r.v0.x; vs[1] -= r.v0.y; vs[2]  -= r.v0.z; vs[3]  -= r.v0.w;
        vs[4] -= r.v1.x; vs[5] -= r.v1.y; vs[6]  -= r.v1.z; vs[7]  -= r.v1.w;
        vs[8] -= r.v2.x; vs[9] -= r.v2.y; vs[10] -= r.v2.z; vs[11] -= r.v2.w;
    }
}

// ---------------- Stage 2: a/b box-blur (register sweep) + combine ----------------
__global__ __launch_bounds__(NWARP * 32)
void gf_s2(const float* __restrict__ gd, float* __restrict__ out) {
    const int b = blockIdx.z;
    const int lane = threadIdx.x & 31;
    const int warp = threadIdx.x >> 5;
    const int tile = blockIdx.x * NWARP + warp;
    const int xout0 = tile * CPW;
    if (xout0 >= WW) return;
    const int x = xout0 + lane - 2;
    const int xr = refl(x, WW);
    const int y0 = blockIdx.y * SEG;
    const int base = b * PLANE + xr;

    float vs[12];
#pragma unroll
    for (int k = 0; k < 12; k++) vs[k] = 0.f;

#pragma unroll
    for (int dy = -2; dy < 2; dy++) {
        RowAB r = loadAB(base + refl(y0 + dy, HH) * WW);
        applyAB<true>(vs, r);
    }

    const bool valid = (lane >= 2) && (lane < 30) && (x < WW);
    const float* gb = gd + b * 3 * PLANE + x;
    float* ob = out + b * 3 * PLANE + x;

    for (int y = y0; y < y0 + SEG; y++) {
        RowAB radd = loadAB(base + refl(y + 2, HH) * WW);
        RowAB rsub = loadAB(base + refl(y - 2, HH) * WW);
        applyAB<true>(vs, radd);

        float M[12];
#pragma unroll
        for (int k = 0; k < 12; k++) M[k] = hsum5(vs[k]);

        if (valid) {
            const int o = y * WW;
            const float g0 = __ldg(gb + o);
            const float g1 = __ldg(gb + o + PLANE);
            const float g2 = __ldg(gb + o + 2 * PLANE);
            const float inv = 1.0f / 25.0f;
            ob[o]             = (g0 * M[0] + g1 * M[3] + g2 * M[6] + M[9])  * inv;
            ob[o + PLANE]     = (g0 * M[1] + g1 * M[4] + g2 * M[7] + M[10]) * inv;
            ob[o + 2 * PLANE] = (g0 * M[2] + g1 * M[5] + g2 * M[8] + M[11]) * inv;
        }

        applyAB<false>(vs, rsub);
    }
}

extern "C" void kernel_launch(void* const* d_in, const int* in_sizes, int n_in,
                              void* d_out, int out_size) {
    const float* gd = (const float*)d_in[0];
    const float* pd = (const float*)d_in[1];
    float* out = (float*)d_out;

    const int tiles = (WW + CPW - 1) / CPW;            // 19
    const int gx = (tiles + NWARP - 1) / NWARP;        // 5
    dim3 grid(gx, HH / SEG, BB);
    dim3 blk(NWARP * 32);
    gf_s1<<<grid, blk>>>(gd, pd);
    gf_s2<<<grid, blk>>>(gd, out);
}

// round 6
// speedup vs baseline: 2.1251x; 1.1045x over previous
#include <cuda_runtime.h>

#define HH 512
#define WW 512
#define BB 8
#define PLANE (HH * WW)
#define CPW 24       // output columns per warp (32 lanes - 8 halo)
#define SEG 64       // output rows swept per warp
#define STEPS (SEG + 4)
#define NWARP 4

__device__ __forceinline__ int refl(int q, int n) {
    if (q < 0) q = -q;
    if (q >= n) q = 2 * n - 2 - q;
    return q;
}

// Horizontal 5-tap sum across warp lanes (lane = column): 3 shuffles + 3 adds.
__device__ __forceinline__ float hsum5(float v) {
    const unsigned m = 0xffffffffu;
    float s1 = v + __shfl_down_sync(m, v, 1);
    return __shfl_up_sync(m, s1, 2) + s1 + __shfl_down_sync(m, v, 2);
}

struct Row6 { float g0, g1, g2, p0, p1, p2; };

__device__ __forceinline__ Row6 load6(const float* __restrict__ gb,
                                      const float* __restrict__ pb, int o) {
    Row6 r;
    r.g0 = __ldg(gb + o); r.g1 = __ldg(gb + o + PLANE); r.g2 = __ldg(gb + o + 2 * PLANE);
    r.p0 = __ldg(pb + o); r.p1 = __ldg(pb + o + PLANE); r.p2 = __ldg(pb + o + 2 * PLANE);
    return r;
}

template<bool ADD>
__device__ __forceinline__ void apply6(float vs[21], const Row6& r) {
    const float s = ADD ? 1.f : -1.f;
    const float sg0 = s * r.g0, sg1 = s * r.g1, sg2 = s * r.g2;
    const float sp0 = s * r.p0, sp1 = s * r.p1, sp2 = s * r.p2;
    vs[0] += sg0; vs[1] += sg1; vs[2] += sg2;
    vs[3] += sp0; vs[4] += sp1; vs[5] += sp2;
    vs[6]  = fmaf(sg0, r.g0, vs[6]);  vs[7]  = fmaf(sg0, r.g1, vs[7]);  vs[8]  = fmaf(sg0, r.g2, vs[8]);
    vs[9]  = fmaf(sg1, r.g1, vs[9]);  vs[10] = fmaf(sg1, r.g2, vs[10]); vs[11] = fmaf(sg2, r.g2, vs[11]);
    vs[12] = fmaf(sg0, r.p0, vs[12]); vs[13] = fmaf(sg0, r.p1, vs[13]); vs[14] = fmaf(sg0, r.p2, vs[14]);
    vs[15] = fmaf(sg1, r.p0, vs[15]); vs[16] = fmaf(sg1, r.p1, vs[16]); vs[17] = fmaf(sg1, r.p2, vs[17]);
    vs[18] = fmaf(sg2, r.p0, vs[18]); vs[19] = fmaf(sg2, r.p1, vs[19]); vs[20] = fmaf(sg2, r.p2, vs[20]);
}

__global__ __launch_bounds__(NWARP * 32, 3)
void gf_fused(const float* __restrict__ gd, const float* __restrict__ pd,
              float* __restrict__ out) {
    const int b = blockIdx.z;
    const int lane = threadIdx.x & 31;
    const int warp = threadIdx.x >> 5;
    const int tile = blockIdx.x * NWARP + warp;
    const int x0 = tile * CPW;
    if (x0 >= WW) return;                      // warp-uniform
    const int x = x0 - 4 + lane;               // this lane's column
    const int xr = refl(x, WW);
    const int y0 = blockIdx.y * SEG;

    const float* gb = gd + b * 3 * PLANE + xr;
    const float* pb = pd + b * 3 * PLANE + xr;

    float vs[21];
#pragma unroll
    for (int k = 0; k < 21; k++) vs[k] = 0.f;

    // Preload product window rows refl(y0-4 .. y0-1).
#pragma unroll
    for (int dy = -4; dy < 0; dy++) {
        Row6 r = load6(gb, pb, refl(y0 + dy, HH) * WW);
        apply6<true>(vs, r);
    }

    float ring[5][12];                          // last 5 rows of h-summed a/b
    const bool ovalid = (lane >= 4) && (lane < 28) && (x < WW);
    const float* gout = gd + b * 3 * PLANE + x; // guidance at true column
    float* ob = out + b * 3 * PLANE + x;
    const float inv = 1.0f / 25.0f;
    const float eps = 1e-4f;

    for (int chunk = 0; chunk < STEPS; chunk += 5) {
#pragma unroll
        for (int ph = 0; ph < 5; ph++) {
            const int st = chunk + ph;
            if (st < STEPS) {
                const int r = y0 - 2 + st;      // ab-row being produced
                Row6 radd = load6(gb, pb, refl(r + 2, HH) * WW);
                Row6 rsub = load6(gb, pb, refl(r - 2, HH) * WW);
                apply6<true>(vs, radd);

                float m[21];
#pragma unroll
                for (int k = 0; k < 21; k++) m[k] = hsum5(vs[k]);

                const float mI0 = m[0] * inv, mI1 = m[1] * inv, mI2 = m[2] * inv;
                const float mp0 = m[3] * inv, mp1 = m[4] * inv, mp2 = m[5] * inv;

                const float a00 = m[6]  * inv - mI0 * mI0 + eps;
                const float a01 = m[7]  * inv - mI0 * mI1;
                const float a02 = m[8]  * inv - mI0 * mI2;
                const float a11 = m[9]  * inv - mI1 * mI1 + eps;
                const float a12 = m[10] * inv - mI1 * mI2;
                const float a22 = m[11] * inv - mI2 * mI2 + eps;

                const float c00 = m[12] * inv - mI0 * mp0, c01 = m[13] * inv - mI0 * mp1, c02 = m[14] * inv - mI0 * mp2;
                const float c10 = m[15] * inv - mI1 * mp0, c11 = m[16] * inv - mI1 * mp1, c12 = m[17] * inv - mI1 * mp2;
                const float c20 = m[18] * inv - mI2 * mp0, c21 = m[19] * inv - mI2 * mp1, c22 = m[20] * inv - mI2 * mp2;

                float i00 = a11 * a22 - a12 * a12;
                float i01 = a02 * a12 - a01 * a22;
                float i02 = a01 * a12 - a02 * a11;
                float i11 = a00 * a22 - a02 * a02;
                float i12 = a01 * a02 - a00 * a12;
                float i22 = a00 * a11 - a01 * a01;
                const float det = a00 * i00 + a01 * i01 + a02 * i02;
                const float rd = 1.0f / det;
                i00 *= rd; i01 *= rd; i02 *= rd; i11 *= rd; i12 *= rd; i22 *= rd;

                float ab[12];
                ab[0]  = i00 * c00 + i01 * c10 + i02 * c20;   // A00
                ab[1]  = i00 * c01 + i01 * c11 + i02 * c21;   // A01
                ab[2]  = i00 * c02 + i01 * c12 + i02 * c22;   // A02
                ab[3]  = i01 * c00 + i11 * c10 + i12 * c20;   // A10
                ab[4]  = i01 * c01 + i11 * c11 + i12 * c21;   // A11
                ab[5]  = i01 * c02 + i11 * c12 + i12 * c22;   // A12
                ab[6]  = i02 * c00 + i12 * c10 + i22 * c20;   // A20
                ab[7]  = i02 * c01 + i12 * c11 + i22 * c21;   // A21
                ab[8]  = i02 * c02 + i12 * c12 + i22 * c22;   // A22
                ab[9]  = mp0 - (ab[0] * mI0 + ab[3] * mI1 + ab[6] * mI2);  // b0
                ab[10] = mp1 - (ab[1] * mI0 + ab[4] * mI1 + ab[7] * mI2);  // b1
                ab[11] = mp2 - (ab[2] * mI0 + ab[5] * mI1 + ab[8] * mI2);  // b2

                // Horizontal 5-tap of a/b, push into static ring slot.
#pragma unroll
                for (int k = 0; k < 12; k++) ring[ph][k] = hsum5(ab[k]);

                const int yout = r - 2;
                if (yout >= y0) {               // ring holds rows yout-2..yout+2
                    float M[12];
#pragma unroll
                    for (int k = 0; k < 12; k++)
                        M[k] = ring[0][k] + ring[1][k] + ring[2][k]
                             + ring[3][k] + ring[4][k];
                    if (ovalid) {
                        const int o = yout * WW;
                        const float g0 = __ldg(gout + o);
                        const float g1 = __ldg(gout + o + PLANE);
                        const float g2 = __ldg(gout + o + 2 * PLANE);
                        ob[o]             = (g0 * M[0] + g1 * M[3] + g2 * M[6] + M[9])  * inv;
                        ob[o + PLANE]     = (g0 * M[1] + g1 * M[4] + g2 * M[7] + M[10]) * inv;
                        ob[o + 2 * PLANE] = (g0 * M[2] + g1 * M[5] + g2 * M[8] + M[11]) * inv;
                    }
                }

                apply6<false>(vs, rsub);
            }
        }
    }
}

extern "C" void kernel_launch(void* const* d_in, const int* in_sizes, int n_in,
                              void* d_out, int out_size) {
    const float* gd = (const float*)d_in[0];
    const float* pd = (const float*)d_in[1];
    float* out = (float*)d_out;

    const int tiles = (WW + CPW - 1) / CPW;            // 22
    const int gx = (tiles + NWARP - 1) / NWARP;        // 6
    dim3 grid(gx, HH / SEG, BB);
    dim3 blk(NWARP * 32);
    gf_fused<<<grid, blk>>>(gd, pd, out);
}